// round 1
// baseline (speedup 1.0000x reference)
#include <cuda_runtime.h>

// Problem constants
//   volume: [40,40,40,32] f32, M: [32,32] f32, P: [32,32] f32
//   output Nk: [59319, 32] f32,  b = (k1*39 + k2)*39 + k3
#define NP   39          // pooled dim per axis (40 - 2 + 1)
#define M32  32
#define NB   (39*39*39)  // 59319

#define PI2F 6.2831853071795864769f

// Scratch (no cudaMalloc allowed)
__device__ float g_tab[39 * 1024];   // tab[k][j*32 + i] = cos(k * 2pi / (i*32+j+2))
__device__ float g_PT[1024];         // PT[j*32 + i] = P[i*32 + j]
__device__ float g_MT[1024];         // MT[l*32 + j] = M[j*32 + l]
__device__ float g_x[NB * 32];       // x[b][j]

// ---------------------------------------------------------------------------
// Kernel 0: precompute cos table and transposed P / M
// grid = 40 blocks x 1024 threads. Blocks 0..38 fill g_tab[k], block 39 fills PT/MT.
// ---------------------------------------------------------------------------
__global__ void k_pre(const float* __restrict__ M, const float* __restrict__ P) {
    int k = blockIdx.x;
    int t = threadIdx.x;            // t = j*32 + i
    if (k < 39) {
        int i = t & 31;
        int j = t >> 5;
        float period = (float)(i * 32 + j + 2);
        float invp = PI2F / period;                 // matches jnp f32 pipeline
        g_tab[k * 1024 + t] = cosf((float)k * invp);
    } else {
        // t interpreted as (row_out = t>>5, col_out = t&31); source transposed
        int src = (t & 31) * 32 + (t >> 5);
        g_PT[t] = P[src];
        g_MT[t] = M[src];
    }
}

// ---------------------------------------------------------------------------
// Kernel 1: fused 2x2x2 average pooling + x = pooled @ M^T
// One block per (k1,k2): grid (39, 39), 320 threads.
// ---------------------------------------------------------------------------
__global__ void __launch_bounds__(320) k_x(const float* __restrict__ vol) {
    __shared__ float pooled_s[NP * 36];   // stride 36 floats: 16B aligned, bank-skewed
    __shared__ float MT_s[1024];

    const int k2 = blockIdx.x;
    const int k1 = blockIdx.y;
    const int tid = threadIdx.x;

    for (int t = tid; t < 1024; t += 320) MT_s[t] = g_MT[t];

    // Pooling: thread = (k3, c-quad); 39*8 = 312 active
    if (tid < 312) {
        int k3 = tid >> 3;
        int cq = tid & 7;
        const float* p0 = vol + ((((k1 * 40) + k2) * 40 + k3) * 32 + cq * 4);
        float4 s = make_float4(0.f, 0.f, 0.f, 0.f);
#pragma unroll
        for (int dd = 0; dd < 2; dd++)
#pragma unroll
            for (int hh = 0; hh < 2; hh++)
#pragma unroll
                for (int ww = 0; ww < 2; ww++) {
                    float4 v = *(const float4*)(p0 + ((dd * 40 + hh) * 40 + ww) * 32);
                    s.x += v.x; s.y += v.y; s.z += v.z; s.w += v.w;
                }
        s.x *= 0.125f; s.y *= 0.125f; s.z *= 0.125f; s.w *= 0.125f;
        *(float4*)&pooled_s[k3 * 36 + cq * 4] = s;
    }
    __syncthreads();

    // x[b][j] = sum_l M[j][l] * pooled[l] ; thread = (k3, j-quad)
    if (tid < 312) {
        int k3 = tid >> 3;
        int jq = tid & 7;
        float a0 = 0.f, a1 = 0.f, a2 = 0.f, a3 = 0.f;
#pragma unroll
        for (int l = 0; l < 32; l++) {
            float p = pooled_s[k3 * 36 + l];
            float4 m4 = *(const float4*)&MT_s[l * 32 + jq * 4];  // M[jq*4..+3][l]
            a0 += p * m4.x; a1 += p * m4.y; a2 += p * m4.z; a3 += p * m4.w;
        }
        int b = (k1 * NP + k2) * NP + k3;
        *(float4*)&g_x[b * 32 + jq * 4] = make_float4(a0, a1, a2, a3);
    }
}

// ---------------------------------------------------------------------------
// Kernel 2: main contraction.
// Block = (k1, tile of 4 k2 values). grid (10, 39), 320 threads.
//   A_s[c][j*32+i] = P[i,j]*cos(k1*a)*cos(k2*a)  (shared across 39 k3)
//   x_s[c][k3][j]  staged for broadcast reads
//   c3 streamed from g_tab via LDG.128 (table is L1/L2 resident, reused 4x/tile)
// Thread = (k3, i-quad); accumulates 4 k2 x 4 i outputs.
// ---------------------------------------------------------------------------
__global__ void __launch_bounds__(320) k_main(float* __restrict__ out) {
    __shared__ float A_s[4 * 1024];          // 16 KB
    __shared__ float x_s[4 * 1287];          // [c][k3*33 + j], 20.6 KB

    const int k1  = blockIdx.y;
    const int k2b = blockIdx.x * 4;
    const int nk2 = (k2b + 4 <= NP) ? 4 : (NP - k2b);
    const int tid = threadIdx.x;

    // Stage A (zero for inactive k2 so accumulators stay clean)
    for (int idx = tid; idx < 4096; idx += 320) {
        int c = idx >> 10;
        int t = idx & 1023;
        float a = 0.f;
        if (c < nk2)
            a = g_PT[t] * g_tab[k1 * 1024 + t] * g_tab[(k2b + c) * 1024 + t];
        A_s[idx] = a;
    }
    // Stage x
    for (int idx = tid; idx < 4 * NP * 32; idx += 320) {
        int c = idx / (NP * 32);
        int r = idx - c * (NP * 32);
        int k3 = r >> 5;
        int j  = r & 31;
        float xv = 0.f;
        if (c < nk2)
            xv = g_x[(((k1 * NP) + k2b + c) * NP + k3) * 32 + j];
        x_s[c * 1287 + k3 * 33 + j] = xv;
    }
    __syncthreads();

    if (tid < 312) {
        const int k3 = tid >> 3;
        const int iq = tid & 7;
        float acc[4][4];
#pragma unroll
        for (int c = 0; c < 4; c++) {
            acc[c][0] = 0.f; acc[c][1] = 0.f; acc[c][2] = 0.f; acc[c][3] = 0.f;
        }
        const float4* tab3 = (const float4*)(g_tab + k3 * 1024 + iq * 4);
#pragma unroll
        for (int j = 0; j < 32; j++) {
            float4 c3 = __ldg(tab3 + j * 8);           // tab[k3][j][iq*4..+3]
#pragma unroll
            for (int c = 0; c < 4; c++) {
                float  xv = x_s[c * 1287 + k3 * 33 + j];
                float4 a4 = *(const float4*)&A_s[c * 1024 + j * 32 + iq * 4];
                acc[c][0] += (a4.x * xv) * c3.x;
                acc[c][1] += (a4.y * xv) * c3.y;
                acc[c][2] += (a4.z * xv) * c3.z;
                acc[c][3] += (a4.w * xv) * c3.w;
            }
        }
#pragma unroll
        for (int c = 0; c < 4; c++) {
            if (c < nk2) {
                int b = ((k1 * NP) + k2b + c) * NP + k3;
                *(float4*)&out[b * 32 + iq * 4] =
                    make_float4(acc[c][0], acc[c][1], acc[c][2], acc[c][3]);
            }
        }
    }
}

// ---------------------------------------------------------------------------
extern "C" void kernel_launch(void* const* d_in, const int* in_sizes, int n_in,
                              void* d_out, int out_size) {
    const float* vol = (const float*)d_in[0];   // [40,40,40,32]
    const float* M   = (const float*)d_in[1];   // [32,32]
    const float* P   = (const float*)d_in[2];   // [32,32]
    float* out = (float*)d_out;                 // [59319, 32]

    k_pre <<<40, 1024>>>(M, P);
    k_x   <<<dim3(39, 39), 320>>>(vol);
    k_main<<<dim3(10, 39), 320>>>(out);
}